// round 1
// baseline (speedup 1.0000x reference)
#include <cuda_runtime.h>
#include <cuda_bf16.h>
#include <cstdint>

// Problem constants
#define NB 128      // batches
#define NN 1024     // vector length
#define TS 64       // W tile size
#define XW 256      // pseudo-batch width: [V ; 1-V]
#define WSTRIDE 68  // Wt shared row stride (floats)  -> 4-way store conflicts max
#define VSTRIDE 260 // Vt/Xi shared row stride (floats)

// Shared layout (floats):
//  Wt : [k=0..63][i] stride WSTRIDE     = 64*68  = 4352
//  Vt : [j=0..63][x] stride VSTRIDE     = 64*260 = 16640
//  Xi : [i=0..63][x] stride VSTRIDE     = 64*260 = 16640
//  s  : [256]
#define OFF_WT 0
#define OFF_VT 4352
#define OFF_XI (4352 + 16640)
#define OFF_S  (4352 + 16640 + 16640)
#define SMEM_FLOATS (OFF_S + 256)
#define SMEM_BYTES  (SMEM_FLOATS * 4)

// Packed f32x2 FMA (Blackwell): d = a*b + c elementwise on packed fp32 pairs.
#define FMA2(d, a, b, c) \
    asm("fma.rn.f32x2 %0, %1, %2, %3;" : "=l"(d) : "l"(a), "l"(b), "l"(c))

__device__ __forceinline__ unsigned long long pack2(float f) {
    unsigned long long r;
    unsigned int u = __float_as_uint(f);
    asm("mov.b64 %0, {%1, %1};" : "=l"(r) : "r"(u));
    return r;
}

__device__ __forceinline__ void unpack2(unsigned long long s, float& lo, float& hi) {
    unsigned int a, b;
    asm("mov.b64 {%0, %1}, %2;" : "=r"(a), "=r"(b) : "l"(s));
    lo = __uint_as_float(a);
    hi = __uint_as_float(b);
}

__global__ void zero_out_kernel(float* out) {
    out[threadIdx.x] = 0.0f;
}

// One block per upper-triangle 64x64 tile of W.
// C[i,x] = sum_j U[I0+i, J0+j] * X[x, J0+j],   X = [V ; 1-V]  (x in 0..255)
// contribution to quad[x]: sum_i X[x, I0+i] * C[i,x]
// energy[b] = quad[b] + quad[b+128]  (accumulated via atomics into out[b])
__global__ void __launch_bounds__(256, 1)
potts_quad_kernel(const float* __restrict__ V, const float* __restrict__ W,
                  float* __restrict__ out)
{
    const int ti = blockIdx.y;   // row tile
    const int tj = blockIdx.x;   // col tile
    if (ti > tj) return;         // strictly-lower tiles contribute nothing

    extern __shared__ float sh[];
    float* Wt  = sh + OFF_WT;
    float* Vt  = sh + OFF_VT;
    float* Xi  = sh + OFF_XI;
    float* ssh = sh + OFF_S;

    const int tid = threadIdx.x;
    const int I0 = ti * TS, J0 = tj * TS;

    ssh[tid] = 0.0f;  // blockDim.x == 256 == XW

    // ---- Load W tile, masked to upper triangle, transposed: Wt[j][i] ----
    #pragma unroll
    for (int it = 0; it < 16; ++it) {
        int L = tid + it * 256;          // 0..4095
        int i = L >> 6, j = L & 63;
        int gi = I0 + i, gj = J0 + j;
        float w = (gi <= gj) ? W[gi * NN + gj] : 0.0f;
        Wt[j * WSTRIDE + i] = w;
    }
    // ---- Load Vt[j][x] = X[x][J0+j] ----
    #pragma unroll
    for (int it = 0; it < 64; ++it) {
        int L = tid + it * 256;          // 0..16383
        int x = L >> 6, j = L & 63;
        float v = V[(x & (NB - 1)) * NN + J0 + j];
        if (x >= NB) v = 1.0f - v;
        Vt[j * VSTRIDE + x] = v;
    }
    // ---- Load Xi[i][x] = X[x][I0+i] ----
    #pragma unroll
    for (int it = 0; it < 64; ++it) {
        int L = tid + it * 256;
        int x = L >> 6, i = L & 63;
        float v = V[(x & (NB - 1)) * NN + I0 + i];
        if (x >= NB) v = 1.0f - v;
        Xi[i * VSTRIDE + x] = v;
    }
    __syncthreads();

    // ---- Register-tiled GEMM: 8 i-values x 8 x-values per thread ----
    const int tib = tid & 7;             // i-group 0..7
    const int txb = tid >> 3;            // x-group 0..31
    const int i0 = tib * 8;
    const int x0 = txb * 8;

    unsigned long long acc[8][4];
    #pragma unroll
    for (int ii = 0; ii < 8; ++ii)
        #pragma unroll
        for (int c = 0; c < 4; ++c)
            acc[ii][c] = 0ull;

    const float* WtP = Wt + i0;
    const float* VtP = Vt + x0;

    #pragma unroll 4
    for (int k = 0; k < TS; ++k) {
        const float4 wA = *reinterpret_cast<const float4*>(WtP + k * WSTRIDE);
        const float4 wB = *reinterpret_cast<const float4*>(WtP + k * WSTRIDE + 4);
        const unsigned long long* vp =
            reinterpret_cast<const unsigned long long*>(VtP + k * VSTRIDE);
        const unsigned long long v0 = vp[0];
        const unsigned long long v1 = vp[1];
        const unsigned long long v2 = vp[2];
        const unsigned long long v3 = vp[3];

        const float wv[8] = {wA.x, wA.y, wA.z, wA.w, wB.x, wB.y, wB.z, wB.w};
        #pragma unroll
        for (int ii = 0; ii < 8; ++ii) {
            const unsigned long long wp = pack2(wv[ii]);
            FMA2(acc[ii][0], wp, v0, acc[ii][0]);
            FMA2(acc[ii][1], wp, v1, acc[ii][1]);
            FMA2(acc[ii][2], wp, v2, acc[ii][2]);
            FMA2(acc[ii][3], wp, v3, acc[ii][3]);
        }
    }

    // ---- Epilogue: s[x] += sum_i Xi[i][x] * C[i][x] ----
    #pragma unroll
    for (int c = 0; c < 4; ++c) {
        float sx = 0.0f, sy = 0.0f;
        #pragma unroll
        for (int ii = 0; ii < 8; ++ii) {
            float ax, ay;
            unpack2(acc[ii][c], ax, ay);
            const float2 xv = *reinterpret_cast<const float2*>(
                &Xi[(i0 + ii) * VSTRIDE + x0 + 2 * c]);
            sx += xv.x * ax;
            sy += xv.y * ay;
        }
        atomicAdd(&ssh[x0 + 2 * c], sx);
        atomicAdd(&ssh[x0 + 2 * c + 1], sy);
    }
    __syncthreads();

    // ---- Reduce pseudo-batches into out[b]: quad(v_b) + quad(a_b) ----
    atomicAdd(&out[tid & (NB - 1)], ssh[tid]);
}

extern "C" void kernel_launch(void* const* d_in, const int* in_sizes, int n_in,
                              void* d_out, int out_size) {
    const float* V = (const float*)d_in[0];   // vector       [128,1024]
    const float* W = (const float*)d_in[1];   // interactions [1024,1024]
    // Defensive: disambiguate by element counts (131072 vs 1048576).
    if (n_in >= 2 && in_sizes[0] > in_sizes[1]) {
        V = (const float*)d_in[1];
        W = (const float*)d_in[0];
    }
    float* out = (float*)d_out;

    zero_out_kernel<<<1, NB>>>(out);

    cudaFuncSetAttribute(potts_quad_kernel,
                         cudaFuncAttributeMaxDynamicSharedMemorySize, SMEM_BYTES);
    dim3 grid(NN / TS, NN / TS);   // (16,16); lower tiles early-exit
    potts_quad_kernel<<<grid, 256, SMEM_BYTES>>>(V, W, out);
}

// round 2
// speedup vs baseline: 1.1472x; 1.1472x over previous
#include <cuda_runtime.h>
#include <cuda_bf16.h>
#include <cstdint>

// Problem constants
#define NB 128      // batches
#define NN 1024     // vector length
#define TI 64       // tile rows (i)
#define TJ 32       // tile cols per block (j) -- 64-col tile split into 2 k-halves
#define NT 16       // 1024/64 tiles per dim
#define WS 68       // Wt row stride (floats)
#define VS 132      // Vt/Xi row stride (floats)

// Shared layout (floats)
#define OFF_WT 0                    // Wt[j 0..31][i 0..63]  : 32*68  = 2176
#define OFF_VT 2176                 // Vt[j 0..31][x 0..127] : 32*132 = 4224
#define OFF_XI (2176 + 4224)        // Xi[i 0..63][x 0..127] : 64*132 = 8448
#define OFF_RT (OFF_XI + 8448)      // rt[64]
#define OFF_CT (OFF_RT + 64)        // ct[32]
#define OFF_S  (OFF_CT + 32)        // ssh[128]
#define SMEM_FLOATS (OFF_S + 128)
#define SMEM_BYTES  (SMEM_FLOATS * 4)

// Packed f32x2 FMA (Blackwell)
#define FMA2(d, a, b, c) \
    asm("fma.rn.f32x2 %0, %1, %2, %3;" : "=l"(d) : "l"(a), "l"(b), "l"(c))

__device__ __forceinline__ unsigned long long pack2(float f) {
    unsigned long long r;
    unsigned int u = __float_as_uint(f);
    asm("mov.b64 %0, {%1, %1};" : "=l"(r) : "r"(u));
    return r;
}
__device__ __forceinline__ void unpack2(unsigned long long s, float& lo, float& hi) {
    unsigned int a, b;
    asm("mov.b64 {%0, %1}, %2;" : "=r"(a), "=r"(b) : "l"(s));
    lo = __uint_as_float(a);
    hi = __uint_as_float(b);
}

__global__ void zero_out_kernel(float* out) {
    out[threadIdx.x] = 0.0f;
}

// energy_b = S0 - v_b.(r+c) + 2 * v_b^T U v_b,  U = triu(W)
// One block per (upper-tri 64x64 tile, j-half). 272 blocks total.
__global__ void __launch_bounds__(256, 2)
potts_quad_kernel(const float* __restrict__ V, const float* __restrict__ W,
                  float* __restrict__ out)
{
    // ---- decode (ti, tj, kh) from linear upper-tri block id ----
    int bid = blockIdx.x;
    int kh  = bid & 1;
    int h   = bid >> 1;            // 0..135 upper-tri tile index
    int ti  = 0;
    while (h >= NT - ti) { h -= NT - ti; ++ti; }
    int tj  = ti + h;

    extern __shared__ float sh[];
    float* Wt  = sh + OFF_WT;
    float* Vt  = sh + OFF_VT;
    float* Xi  = sh + OFF_XI;
    float* rt  = sh + OFF_RT;
    float* ct  = sh + OFF_CT;
    float* ssh = sh + OFF_S;

    const int tid = threadIdx.x;
    const int I0 = ti * TI;
    const int J0 = tj * TI + kh * TJ;

    if (tid < NB) ssh[tid] = 0.0f;

    // ---- Load W half-tile, masked to upper triangle, transposed: Wt[j][i] ----
    #pragma unroll
    for (int it = 0; it < 8; ++it) {          // 2048 elems
        int L = tid + it * 256;
        int j = L & 31, i = L >> 5;           // coalesced over j
        int gi = I0 + i, gj = J0 + j;
        float w = (gi <= gj) ? W[gi * NN + gj] : 0.0f;
        Wt[j * WS + i] = w;
    }
    // ---- Vt[j][x] = V[x][J0+j] ----
    #pragma unroll
    for (int it = 0; it < 16; ++it) {         // 4096 elems
        int L = tid + it * 256;
        int j = L & 31, x = L >> 5;           // coalesced over j
        Vt[j * VS + x] = V[x * NN + J0 + j];
    }
    // ---- Xi[i][x] = V[x][I0+i] ----
    #pragma unroll
    for (int it = 0; it < 32; ++it) {         // 8192 elems
        int L = tid + it * 256;
        int i = L & 63, x = L >> 6;           // coalesced over i
        Xi[i * VS + x] = V[x * NN + I0 + i];
    }
    __syncthreads();

    // ---- Register GEMM: 8 i x 4 x per thread, k over 32 j's ----
    const int tib = tid & 7;                  // i-group 0..7
    const int txb = tid >> 3;                 // x-group 0..31
    const int i0 = tib * 8;
    const int x0 = txb * 4;

    unsigned long long acc[8][2];
    #pragma unroll
    for (int ii = 0; ii < 8; ++ii) { acc[ii][0] = 0ull; acc[ii][1] = 0ull; }

    const float* WtP = Wt + i0;
    const float* VtP = Vt + x0;

    #pragma unroll 4
    for (int k = 0; k < TJ; ++k) {
        const float4 wA = *reinterpret_cast<const float4*>(WtP + k * WS);
        const float4 wB = *reinterpret_cast<const float4*>(WtP + k * WS + 4);
        const unsigned long long* vp =
            reinterpret_cast<const unsigned long long*>(VtP + k * VS);
        const unsigned long long v01 = vp[0];
        const unsigned long long v23 = vp[1];

        const float wv[8] = {wA.x, wA.y, wA.z, wA.w, wB.x, wB.y, wB.z, wB.w};
        #pragma unroll
        for (int ii = 0; ii < 8; ++ii) {
            const unsigned long long wp = pack2(wv[ii]);
            FMA2(acc[ii][0], wp, v01, acc[ii][0]);
            FMA2(acc[ii][1], wp, v23, acc[ii][1]);
        }
    }

    // ---- Row/col sums of this W half-tile (for linear + constant terms) ----
    if (tid < 64) {
        float s = 0.0f;
        #pragma unroll 8
        for (int j = 0; j < TJ; ++j) s += Wt[j * WS + tid];
        rt[tid] = s;
    } else if (tid < 96) {
        int j = tid - 64;
        float s = 0.0f;
        #pragma unroll 8
        for (int i = 0; i < TI; ++i) s += Wt[j * WS + i];
        ct[j] = s;
    }

    // ---- Quad epilogue: ssh[x] += 2 * sum_i Xi[i][x] * C[i][x] ----
    #pragma unroll
    for (int c = 0; c < 2; ++c) {
        float sx = 0.0f, sy = 0.0f;
        #pragma unroll
        for (int ii = 0; ii < 8; ++ii) {
            float ax, ay;
            unpack2(acc[ii][c], ax, ay);
            const float2 xv = *reinterpret_cast<const float2*>(
                &Xi[(i0 + ii) * VS + x0 + 2 * c]);
            sx += xv.x * ax;
            sy += xv.y * ay;
        }
        atomicAdd(&ssh[x0 + 2 * c],     2.0f * sx);
        atomicAdd(&ssh[x0 + 2 * c + 1], 2.0f * sy);
    }
    __syncthreads();   // rt/ct + quad contributions visible

    // ---- Linear + constant: ssh[b] += sum_i rt_i*(1 - v[b,I0+i]) - sum_j ct_j*v[b,J0+j] ----
    if (tid < NB) {
        float e = 0.0f;
        #pragma unroll 8
        for (int i = 0; i < TI; ++i) e += rt[i] * (1.0f - Xi[i * VS + tid]);
        #pragma unroll 8
        for (int j = 0; j < TJ; ++j) e -= ct[j] * Vt[j * VS + tid];
        atomicAdd(&ssh[tid], e);
    }
    __syncthreads();

    if (tid < NB) atomicAdd(&out[tid], ssh[tid]);
}

extern "C" void kernel_launch(void* const* d_in, const int* in_sizes, int n_in,
                              void* d_out, int out_size) {
    const float* V = (const float*)d_in[0];   // vector       [128,1024]
    const float* W = (const float*)d_in[1];   // interactions [1024,1024]
    if (n_in >= 2 && in_sizes[0] > in_sizes[1]) {
        V = (const float*)d_in[1];
        W = (const float*)d_in[0];
    }
    float* out = (float*)d_out;

    zero_out_kernel<<<1, NB>>>(out);

    cudaFuncSetAttribute(potts_quad_kernel,
                         cudaFuncAttributeMaxDynamicSharedMemorySize, SMEM_BYTES);
    const int nblocks = (NT * (NT + 1) / 2) * 2;   // 136 upper tiles x 2 k-halves = 272
    potts_quad_kernel<<<nblocks, 256, SMEM_BYTES>>>(V, W, out);
}